// round 10
// baseline (speedup 1.0000x reference)
#include <cuda_runtime.h>
#include <cuda_fp16.h>
#include <cstdint>

#define NREL 8
#define F    128
#define NMAX 100000
#define EMAX 1600000
#define NBUCK (NMAX * NREL)

// Scratch (no allocation allowed)
__device__ __align__(16) __half g_wh[NREL * F * F];  // transposed: [r][n][k]
__device__ int g_cnt[NBUCK + 1];
__device__ int g_off[NBUCK + 1];   // after fill: inclusive segment ends
__device__ int g_eidx[EMAX];       // src per edge, bucket-sorted
__device__ int g_bsum[1024];

// ---------------------------------------------------------------------------
// Fused setup: zero histogram + weight [r][k][n] -> fp16 transposed [r][n][k]
// ---------------------------------------------------------------------------
__global__ void setup_kernel(const float* __restrict__ wgt, int n_w, int nb) {
    int i = blockIdx.x * blockDim.x + threadIdx.x;
    if (i < n_w) {
        int r = i >> 14, rem = i & 16383, k = rem >> 7, nn = rem & 127;
        g_wh[r * 16384 + nn * 128 + k] = __float2half_rn(wgt[i]);
    }
    if (i <= nb) g_cnt[i] = 0;
}

// ---------------------------------------------------------------------------
// Counting sort by key = et*n_nodes + dst (relation-major buckets)
// ---------------------------------------------------------------------------
__global__ void hist_kernel(const int* __restrict__ dst,
                            const int* __restrict__ et, int E, int n_nodes) {
    int e = blockIdx.x * blockDim.x + threadIdx.x;
    if (e < E) atomicAdd(&g_cnt[et[e] * n_nodes + dst[e]], 1);
}

// Pass 1: per-block (1024) exclusive scan; block totals -> g_bsum
__global__ void __launch_bounds__(1024) scan1_kernel(int n) {
    const int tid = threadIdx.x, lane = tid & 31, wid = tid >> 5;
    __shared__ int wsum[32];
    int i = blockIdx.x * 1024 + tid;
    int x = (i < n) ? g_cnt[i] : 0;
    int v = x;
#pragma unroll
    for (int d = 1; d < 32; d <<= 1) {
        int t = __shfl_up_sync(0xFFFFFFFFu, v, d);
        if (lane >= d) v += t;
    }
    if (lane == 31) wsum[wid] = v;
    __syncthreads();
    if (wid == 0) {
        int s = wsum[lane];
        int sv = s;
#pragma unroll
        for (int d = 1; d < 32; d <<= 1) {
            int t = __shfl_up_sync(0xFFFFFFFFu, sv, d);
            if (lane >= d) sv += t;
        }
        wsum[lane] = sv - s;
    }
    __syncthreads();
    if (i < n) g_off[i] = wsum[wid] + v - x;
    if (tid == 1023) g_bsum[blockIdx.x] = wsum[31] + v;
}

// Pass 2: single-block exclusive scan of the <=1024 block totals
__global__ void __launch_bounds__(1024) scan2_kernel(int nblk, int n) {
    const int tid = threadIdx.x, lane = tid & 31, wid = tid >> 5;
    __shared__ int wsum[32];
    int x = (tid < nblk) ? g_bsum[tid] : 0;
    int v = x;
#pragma unroll
    for (int d = 1; d < 32; d <<= 1) {
        int t = __shfl_up_sync(0xFFFFFFFFu, v, d);
        if (lane >= d) v += t;
    }
    if (lane == 31) wsum[wid] = v;
    __syncthreads();
    if (wid == 0) {
        int s = wsum[lane];
        int sv = s;
#pragma unroll
        for (int d = 1; d < 32; d <<= 1) {
            int t = __shfl_up_sync(0xFFFFFFFFu, sv, d);
            if (lane >= d) sv += t;
        }
        wsum[lane] = sv - s;
    }
    __syncthreads();
    if (tid < nblk) g_bsum[tid] = wsum[wid] + v - x;
    if (tid == 1023) g_off[n] = wsum[31] + v;
}

// Pass 3: add block offsets (final exclusive offsets in g_off)
__global__ void scan3_kernel(int n) {
    int i = blockIdx.x * blockDim.x + threadIdx.x;
    if (i < n) g_off[i] += g_bsum[i >> 10];
}

// In-place fill: atomicAdd on g_off; afterwards g_off[k] = inclusive end of
// segment k (= exclusive start of k+1). Segment k start = g_off[k-1] (0 for k=0).
__global__ void fill_kernel(const int* __restrict__ src,
                            const int* __restrict__ dst,
                            const int* __restrict__ et, int E, int n_nodes) {
    int e = blockIdx.x * blockDim.x + threadIdx.x;
    if (e < E) {
        int p = atomicAdd(&g_off[et[e] * n_nodes + dst[e]], 1);
        g_eidx[p] = src[e];
    }
}

// ---------------------------------------------------------------------------
// Fused aggregate + GEMM
// ---------------------------------------------------------------------------
__device__ __forceinline__ uint32_t smem_u32(const void* p) {
    uint32_t a;
    asm("{ .reg .u64 t; cvta.to.shared.u64 t, %1; cvt.u32.u64 %0, t; }" : "=r"(a) : "l"(p));
    return a;
}

__device__ __forceinline__ void mma16816(float c[4], const uint32_t a[4],
                                         const uint32_t b0, const uint32_t b1) {
    asm volatile(
        "mma.sync.aligned.m16n8k16.row.col.f32.f16.f16.f32 "
        "{%0,%1,%2,%3}, {%4,%5,%6,%7}, {%8,%9}, {%0,%1,%2,%3};"
        : "+f"(c[0]), "+f"(c[1]), "+f"(c[2]), "+f"(c[3])
        : "r"(a[0]), "r"(a[1]), "r"(a[2]), "r"(a[3]), "r"(b0), "r"(b1));
}

#define LDSM_X4(r, addr) \
    asm volatile("ldmatrix.sync.aligned.m8n8.x4.shared.b16 {%0,%1,%2,%3}, [%4];" \
                 : "=r"((r)[0]), "=r"((r)[1]), "=r"((r)[2]), "=r"((r)[3]) : "r"(addr))

#define PITCH_B 272
#define TILE_SZ (128 * PITCH_B)   // 34816 B

__device__ __forceinline__ void cpa_tile(uint32_t s_base, const __half* g,
                                         int valid_rows, int tid) {
    const char* gc = reinterpret_cast<const char*>(g);
#pragma unroll
    for (int it = 0; it < 4; it++) {
        int i = tid + it * 512;
        int m = i >> 4, c = i & 15;
        uint32_t s = s_base + m * PITCH_B + c * 16;
        const char* src = gc + m * 256 + c * 16;
        int sz = (m < valid_rows) ? 16 : 0;
        asm volatile("cp.async.cg.shared.global [%0], [%1], 16, %2;"
                     :: "r"(s), "l"(src), "r"(sz) : "memory");
    }
}

// SMEM map: A tile (aggregated H_q), W double buffer
#define OFF_A  0u
#define OFF_W0 34816u
#define OFF_W1 69632u
#define SMEM_SZ 104448

__global__ void __launch_bounds__(512, 1) fused_kernel(
    const float* __restrict__ feat, float* __restrict__ out, int n_nodes) {
    extern __shared__ __align__(128) char smem[];
    const uint32_t sb = smem_u32(smem);
    const int tid = threadIdx.x, wid = tid >> 5, lane = tid & 31;
    const int m0 = blockIdx.x * 128;

    // Prologue: W_0 into buffer 0
    cpa_tile(sb + OFF_W0, g_wh, 128, tid);
    asm volatile("cp.async.commit_group;" ::: "memory");

    const int wm = (wid >> 1) * 16;
    const int wn = (wid & 1) * 64;
    const uint32_t a_off =
        (uint32_t)((wm + (lane & 15)) * PITCH_B + ((lane >> 4) * 8) * 2);
    const int b_row = (lane & 7) + ((lane >> 3) & 1) * 8;
    const uint32_t b_koff = (uint32_t)(((lane >> 4) * 8) * 2);

    float acc[8][4];
#pragma unroll
    for (int i = 0; i < 8; i++)
#pragma unroll
        for (int j = 0; j < 4; j++) acc[i][j] = 0.f;

    const int row0 = wid * 8;  // each warp aggregates 8 consecutive dst rows

    for (int q = 0; q < NREL; q++) {
        if (q < 7) {  // prefetch next W (hidden under aggregation)
            cpa_tile(sb + (((q + 1) & 1) ? OFF_W1 : OFF_W0),
                     g_wh + (size_t)(q + 1) * F * F, 128, tid);
            asm volatile("cp.async.commit_group;" ::: "memory");
        }

        // --- Aggregate relation q's 128 H-rows into A smem (fp16) ---
        // Buckets q*n_nodes + (m0+row) are consecutive: chain beg = prev end.
        int prev_end = -1;
#pragma unroll
        for (int rr = 0; rr < 8; rr++) {
            const int row = row0 + rr;
            const int node = m0 + row;
            float4 a4 = make_float4(0.f, 0.f, 0.f, 0.f);
            if (node < n_nodes) {
                const int bucket = q * n_nodes + node;
                int beg = (prev_end >= 0) ? prev_end
                          : (bucket ? g_off[bucket - 1] : 0);
                int end = g_off[bucket];
                prev_end = end;
                int j = beg;
                for (; j + 4 <= end; j += 4) {
                    int s0 = g_eidx[j], s1 = g_eidx[j + 1];
                    int s2 = g_eidx[j + 2], s3 = g_eidx[j + 3];
                    float4 a = reinterpret_cast<const float4*>(feat + (size_t)s0 * F)[lane];
                    float4 b = reinterpret_cast<const float4*>(feat + (size_t)s1 * F)[lane];
                    float4 c = reinterpret_cast<const float4*>(feat + (size_t)s2 * F)[lane];
                    float4 e = reinterpret_cast<const float4*>(feat + (size_t)s3 * F)[lane];
                    a4.x += (a.x + b.x) + (c.x + e.x);
                    a4.y += (a.y + b.y) + (c.y + e.y);
                    a4.z += (a.z + b.z) + (c.z + e.z);
                    a4.w += (a.w + b.w) + (c.w + e.w);
                }
                for (; j < end; j++) {
                    int s = g_eidx[j];
                    float4 a = reinterpret_cast<const float4*>(feat + (size_t)s * F)[lane];
                    a4.x += a.x; a4.y += a.y; a4.z += a.z; a4.w += a.w;
                }
            }
            __half2 h01 = __halves2half2(__float2half_rn(a4.x), __float2half_rn(a4.y));
            __half2 h23 = __halves2half2(__float2half_rn(a4.z), __float2half_rn(a4.w));
            uint2 u;
            u.x = *reinterpret_cast<uint32_t*>(&h01);
            u.y = *reinterpret_cast<uint32_t*>(&h23);
            *reinterpret_cast<uint2*>(smem + OFF_A + row * PITCH_B + lane * 8) = u;
        }

        // Wait for W_q (allow W_{q+1} still in flight), sync A visibility
        if (q < 7) asm volatile("cp.async.wait_group 1;" ::: "memory");
        else       asm volatile("cp.async.wait_group 0;" ::: "memory");
        __syncthreads();

        // --- MMA: acc += A(H_q) x W_q ---
        const uint32_t bb = sb + ((q & 1) ? OFF_W1 : OFF_W0);
#pragma unroll
        for (int kk = 0; kk < 8; kk++) {
            const uint32_t k2 = (uint32_t)(kk * 32);
            uint32_t ah[4];
            LDSM_X4(ah, sb + OFF_A + a_off + k2);
#pragma unroll
            for (int nb = 0; nb < 4; nb++) {
                const uint32_t baddr =
                    bb + (uint32_t)((wn + nb * 16 + b_row) * PITCH_B) + b_koff + k2;
                uint32_t bh[4];
                LDSM_X4(bh, baddr);
                mma16816(acc[nb * 2],     ah, bh[0], bh[2]);
                mma16816(acc[nb * 2 + 1], ah, bh[1], bh[3]);
            }
        }
        __syncthreads();  // A consumed before next relation overwrites it
    }

    // Epilogue: single write of the relation-summed tile
    const int r0 = wm + (lane >> 2);
    const bool ok0 = (m0 + r0) < n_nodes;
    const bool ok1 = (m0 + r0 + 8) < n_nodes;
    float* cp = out + (size_t)m0 * F;
#pragma unroll
    for (int ns = 0; ns < 8; ns++) {
        const int col = wn + ns * 8 + (lane & 3) * 2;
        if (ok0) *(float2*)&cp[(size_t)r0 * F + col] =
            make_float2(acc[ns][0], acc[ns][1]);
        if (ok1) *(float2*)&cp[(size_t)(r0 + 8) * F + col] =
            make_float2(acc[ns][2], acc[ns][3]);
    }
}

// ---------------------------------------------------------------------------
extern "C" void kernel_launch(void* const* d_in, const int* in_sizes, int n_in,
                              void* d_out, int out_size) {
    const float* feat   = (const float*)d_in[0];
    const float* weight = (const float*)d_in[1];
    const int*   src    = (const int*)d_in[2];
    const int*   dst    = (const int*)d_in[3];
    const int*   et     = (const int*)d_in[4];

    const int n_nodes = in_sizes[0] / F;
    const int n_w     = in_sizes[1];
    const int E       = in_sizes[2];
    float* out = (float*)d_out;

    const int nb = n_nodes * NREL;            // 800K buckets
    const int nblk = (nb + 1023) / 1024;      // scan blocks (<=1024)

    // Setup: zero histogram + fp16 transposed weights
    setup_kernel<<<(nb + 256) / 256, 256>>>(weight, n_w, nb);

    // Counting sort by (et, dst)
    hist_kernel<<<(E + 255) / 256, 256>>>(dst, et, E, n_nodes);
    scan1_kernel<<<nblk, 1024>>>(nb);
    scan2_kernel<<<1, 1024>>>(nblk, nb);
    scan3_kernel<<<(nb + 255) / 256, 256>>>(nb);
    fill_kernel<<<(E + 255) / 256, 256>>>(src, dst, et, E, n_nodes);

    // Fused gather-aggregate + relation-sum GEMM
    cudaFuncSetAttribute(fused_kernel,
                         cudaFuncAttributeMaxDynamicSharedMemorySize, SMEM_SZ);
    fused_kernel<<<(n_nodes + 127) / 128, 512, SMEM_SZ>>>(feat, out, n_nodes);
}

// round 11
// speedup vs baseline: 1.2620x; 1.2620x over previous
#include <cuda_runtime.h>
#include <cuda_fp16.h>
#include <cstdint>

#define NREL 8
#define F    128
#define NMAX 100000
#define EMAX 1600000
#define NBUCK (NMAX * NREL)

// Scratch (no allocation allowed)
__device__ __align__(16) __half g_Hh[(size_t)NREL * NMAX * F];  // 204.8 MB
__device__ __align__(16) __half g_wh[NREL * F * F];  // transposed: [r][n][k]
__device__ int g_cnt[NBUCK + 1];   // histogram, then block-local exclusive offsets
__device__ int g_eidx[EMAX];       // src per edge, bucket-sorted
__device__ int g_bsum[1024];       // per-1024-chunk base offsets

// ---------------------------------------------------------------------------
// Fused setup: zero histogram + weight [r][k][n] -> fp16 transposed [r][n][k]
// ---------------------------------------------------------------------------
__global__ void setup_kernel(const float* __restrict__ wgt, int n_w, int nb) {
    int i = blockIdx.x * blockDim.x + threadIdx.x;
    if (i < n_w) {
        int r = i >> 14, rem = i & 16383, k = rem >> 7, nn = rem & 127;
        g_wh[r * 16384 + nn * 128 + k] = __float2half_rn(wgt[i]);
    }
    if (i <= nb) g_cnt[i] = 0;
}

// ---------------------------------------------------------------------------
// Counting sort by key = et*n_nodes + dst (bucket index == H row index)
// ---------------------------------------------------------------------------
__global__ void hist_kernel(const int* __restrict__ dst,
                            const int* __restrict__ et, int E, int n_nodes) {
    int e = blockIdx.x * blockDim.x + threadIdx.x;
    if (e < E) atomicAdd(&g_cnt[et[e] * n_nodes + dst[e]], 1);
}

// Pass 1: per-block (1024) exclusive scan in place; block totals -> g_bsum
__global__ void __launch_bounds__(1024) scan1_kernel(int n) {
    const int tid = threadIdx.x, lane = tid & 31, wid = tid >> 5;
    __shared__ int wsum[32];
    int i = blockIdx.x * 1024 + tid;
    int x = (i < n) ? g_cnt[i] : 0;
    int v = x;
#pragma unroll
    for (int d = 1; d < 32; d <<= 1) {
        int t = __shfl_up_sync(0xFFFFFFFFu, v, d);
        if (lane >= d) v += t;
    }
    if (lane == 31) wsum[wid] = v;
    __syncthreads();
    if (wid == 0) {
        int s = wsum[lane];
        int sv = s;
#pragma unroll
        for (int d = 1; d < 32; d <<= 1) {
            int t = __shfl_up_sync(0xFFFFFFFFu, sv, d);
            if (lane >= d) sv += t;
        }
        wsum[lane] = sv - s;
    }
    __syncthreads();
    if (i < n) g_cnt[i] = wsum[wid] + v - x;   // block-local exclusive
    if (tid == 1023) g_bsum[blockIdx.x] = wsum[31] + v;
}

// Pass 2: single-block exclusive scan of the <=1024 block totals (in place)
__global__ void __launch_bounds__(1024) scan2_kernel(int nblk) {
    const int tid = threadIdx.x, lane = tid & 31, wid = tid >> 5;
    __shared__ int wsum[32];
    int x = (tid < nblk) ? g_bsum[tid] : 0;
    int v = x;
#pragma unroll
    for (int d = 1; d < 32; d <<= 1) {
        int t = __shfl_up_sync(0xFFFFFFFFu, v, d);
        if (lane >= d) v += t;
    }
    if (lane == 31) wsum[wid] = v;
    __syncthreads();
    if (wid == 0) {
        int s = wsum[lane];
        int sv = s;
#pragma unroll
        for (int d = 1; d < 32; d <<= 1) {
            int t = __shfl_up_sync(0xFFFFFFFFu, sv, d);
            if (lane >= d) sv += t;
        }
        wsum[lane] = sv - s;
    }
    __syncthreads();
    if (tid < nblk) g_bsum[tid] = wsum[wid] + v - x;
}

// Fill: final position = local atomicAdd + chunk base. After this kernel,
// g_cnt[k] = block-local inclusive end; true end = g_cnt[k] + g_bsum[k>>10].
__global__ void fill_kernel(const int* __restrict__ src,
                            const int* __restrict__ dst,
                            const int* __restrict__ et, int E, int n_nodes) {
    int e = blockIdx.x * blockDim.x + threadIdx.x;
    if (e < E) {
        int key = et[e] * n_nodes + dst[e];
        int p = atomicAdd(&g_cnt[key], 1) + g_bsum[key >> 10];
        g_eidx[p] = src[e];
    }
}

// ---------------------------------------------------------------------------
// Aggregate: one warp per bucket (= H row). Gather fp32 feat rows (L2-hot),
// fp32 accumulate, fp16 round, coalesced H row write.
// ---------------------------------------------------------------------------
__global__ void aggregate_kernel(const float* __restrict__ feat, int nb) {
    int w = (blockIdx.x * blockDim.x + threadIdx.x) >> 5;
    int lane = threadIdx.x & 31;
    if (w >= nb) return;
    int end = g_cnt[w] + g_bsum[w >> 10];
    int beg = w ? (g_cnt[w - 1] + g_bsum[(w - 1) >> 10]) : 0;
    float4 acc = make_float4(0.f, 0.f, 0.f, 0.f);
    int j = beg;
    for (; j + 4 <= end; j += 4) {
        int s0 = g_eidx[j], s1 = g_eidx[j + 1];
        int s2 = g_eidx[j + 2], s3 = g_eidx[j + 3];
        float4 a = reinterpret_cast<const float4*>(feat + (size_t)s0 * F)[lane];
        float4 b = reinterpret_cast<const float4*>(feat + (size_t)s1 * F)[lane];
        float4 c = reinterpret_cast<const float4*>(feat + (size_t)s2 * F)[lane];
        float4 e = reinterpret_cast<const float4*>(feat + (size_t)s3 * F)[lane];
        acc.x += (a.x + b.x) + (c.x + e.x);
        acc.y += (a.y + b.y) + (c.y + e.y);
        acc.z += (a.z + b.z) + (c.z + e.z);
        acc.w += (a.w + b.w) + (c.w + e.w);
    }
    for (; j < end; j++) {
        int s = g_eidx[j];
        float4 a = reinterpret_cast<const float4*>(feat + (size_t)s * F)[lane];
        acc.x += a.x; acc.y += a.y; acc.z += a.z; acc.w += a.w;
    }
    __half2 a01 = __halves2half2(__float2half_rn(acc.x), __float2half_rn(acc.y));
    __half2 a23 = __halves2half2(__float2half_rn(acc.z), __float2half_rn(acc.w));
    uint2 uh;
    uh.x = *reinterpret_cast<uint32_t*>(&a01);
    uh.y = *reinterpret_cast<uint32_t*>(&a23);
    // bucket index == H row index: consecutive warps -> consecutive rows
    *reinterpret_cast<uint2*>(g_Hh + (size_t)w * F + lane * 4) = uh;
}

// ---------------------------------------------------------------------------
// Legacy-pipe GEMM building blocks
// ---------------------------------------------------------------------------
__device__ __forceinline__ uint32_t smem_u32(const void* p) {
    uint32_t a;
    asm("{ .reg .u64 t; cvta.to.shared.u64 t, %1; cvt.u32.u64 %0, t; }" : "=r"(a) : "l"(p));
    return a;
}

__device__ __forceinline__ void mma16816(float c[4], const uint32_t a[4],
                                         const uint32_t b0, const uint32_t b1) {
    asm volatile(
        "mma.sync.aligned.m16n8k16.row.col.f32.f16.f16.f32 "
        "{%0,%1,%2,%3}, {%4,%5,%6,%7}, {%8,%9}, {%0,%1,%2,%3};"
        : "+f"(c[0]), "+f"(c[1]), "+f"(c[2]), "+f"(c[3])
        : "r"(a[0]), "r"(a[1]), "r"(a[2]), "r"(a[3]), "r"(b0), "r"(b1));
}

#define LDSM_X4(r, addr) \
    asm volatile("ldmatrix.sync.aligned.m8n8.x4.shared.b16 {%0,%1,%2,%3}, [%4];" \
                 : "=r"((r)[0]), "=r"((r)[1]), "=r"((r)[2]), "=r"((r)[3]) : "r"(addr))

#define PITCH_B 272
#define TILE_SZ (128 * PITCH_B)   // 34816 B

__device__ __forceinline__ void cpa_tile(uint32_t s_base, const __half* g,
                                         int valid_rows, int tid) {
    const char* gc = reinterpret_cast<const char*>(g);
#pragma unroll
    for (int it = 0; it < 4; it++) {
        int i = tid + it * 512;
        int m = i >> 4, c = i & 15;
        uint32_t s = s_base + m * PITCH_B + c * 16;
        const char* src = gc + m * 256 + c * 16;
        int sz = (m < valid_rows) ? 16 : 0;
        asm volatile("cp.async.cg.shared.global [%0], [%1], 16, %2;"
                     :: "r"(s), "l"(src), "r"(sz) : "memory");
    }
}

// SMEM map: A x2 buffers, B x2 buffers
#define OFF_A0 0u
#define OFF_A1 34816u
#define OFF_B0 69632u
#define OFF_B1 104448u
#define SMEM_SZ 139264

// ---------------------------------------------------------------------------
// GEMM: per CTA one 128-row dst tile; loop 8 relations with A=H_r, B=W_r;
// accumulate across relations in registers; write out once.
// ---------------------------------------------------------------------------
__global__ void __launch_bounds__(512, 1) gemm_kernel(float* __restrict__ out,
                                                      int n_nodes) {
    extern __shared__ __align__(128) char smem[];
    const uint32_t sb = smem_u32(smem);
    const int tid = threadIdx.x, wid = tid >> 5, lane = tid & 31;
    const int m0 = blockIdx.x * 128;
    const int valid = n_nodes - m0;

    // Prologue: relation 0 into buffer 0
    cpa_tile(sb + OFF_A0, g_Hh + (size_t)m0 * F, valid, tid);
    cpa_tile(sb + OFF_B0, g_wh, 128, tid);
    asm volatile("cp.async.commit_group;" ::: "memory");

    const int wm = (wid >> 1) * 16;
    const int wn = (wid & 1) * 64;
    const uint32_t a_off =
        (uint32_t)((wm + (lane & 15)) * PITCH_B + ((lane >> 4) * 8) * 2);
    const int b_row = (lane & 7) + ((lane >> 3) & 1) * 8;
    const uint32_t b_koff = (uint32_t)(((lane >> 4) * 8) * 2);

    float acc[8][4];
#pragma unroll
    for (int i = 0; i < 8; i++)
#pragma unroll
        for (int j = 0; j < 4; j++) acc[i][j] = 0.f;

    for (int q = 0; q < NREL; q++) {
        if (q < 7) {  // prefetch next relation into the other buffer
            const int nb1 = (q + 1) & 1;
            cpa_tile(sb + (nb1 ? OFF_A1 : OFF_A0),
                     g_Hh + ((size_t)(q + 1) * n_nodes + m0) * F, valid, tid);
            cpa_tile(sb + (nb1 ? OFF_B1 : OFF_B0),
                     g_wh + (size_t)(q + 1) * F * F, 128, tid);
            asm volatile("cp.async.commit_group;" ::: "memory");
            asm volatile("cp.async.wait_group 1;" ::: "memory");
        } else {
            asm volatile("cp.async.wait_group 0;" ::: "memory");
        }
        __syncthreads();

        const uint32_t ab = sb + ((q & 1) ? OFF_A1 : OFF_A0);
        const uint32_t bb = sb + ((q & 1) ? OFF_B1 : OFF_B0);

#pragma unroll
        for (int kk = 0; kk < 8; kk++) {
            const uint32_t k2 = (uint32_t)(kk * 32);
            uint32_t ah[4];
            LDSM_X4(ah, ab + a_off + k2);
#pragma unroll
            for (int nb = 0; nb < 4; nb++) {
                const uint32_t baddr =
                    bb + (uint32_t)((wn + nb * 16 + b_row) * PITCH_B) + b_koff + k2;
                uint32_t bh[4];
                LDSM_X4(bh, baddr);
                mma16816(acc[nb * 2],     ah, bh[0], bh[2]);
                mma16816(acc[nb * 2 + 1], ah, bh[1], bh[3]);
            }
        }
        __syncthreads();  // all warps done with buf (q&1) before refill
    }

    // Epilogue: single write of the relation-summed tile
    const int r0 = wm + (lane >> 2);
    const bool ok0 = (m0 + r0) < n_nodes;
    const bool ok1 = (m0 + r0 + 8) < n_nodes;
    float* cp = out + (size_t)m0 * F;
#pragma unroll
    for (int ns = 0; ns < 8; ns++) {
        const int col = wn + ns * 8 + (lane & 3) * 2;
        if (ok0) *(float2*)&cp[(size_t)r0 * F + col] =
            make_float2(acc[ns][0], acc[ns][1]);
        if (ok1) *(float2*)&cp[(size_t)(r0 + 8) * F + col] =
            make_float2(acc[ns][2], acc[ns][3]);
    }
}

// ---------------------------------------------------------------------------
extern "C" void kernel_launch(void* const* d_in, const int* in_sizes, int n_in,
                              void* d_out, int out_size) {
    const float* feat   = (const float*)d_in[0];
    const float* weight = (const float*)d_in[1];
    const int*   src    = (const int*)d_in[2];
    const int*   dst    = (const int*)d_in[3];
    const int*   et     = (const int*)d_in[4];

    const int n_nodes = in_sizes[0] / F;
    const int n_w     = in_sizes[1];
    const int E       = in_sizes[2];
    float* out = (float*)d_out;

    const int nb = n_nodes * NREL;            // 800K buckets
    const int nblk = (nb + 1023) / 1024;      // scan blocks (<=1024)

    // Setup: zero histogram + fp16 transposed weights
    setup_kernel<<<(nb + 256) / 256, 256>>>(weight, n_w, nb);

    // Counting sort by (et, dst); scan3 folded into fill/aggregate via g_bsum
    hist_kernel<<<(E + 255) / 256, 256>>>(dst, et, E, n_nodes);
    scan1_kernel<<<nblk, 1024>>>(nb);
    scan2_kernel<<<1, 1024>>>(nblk);
    fill_kernel<<<(E + 255) / 256, 256>>>(src, dst, et, E, n_nodes);

    // Aggregate feat into H rows (bucket order), fp16
    aggregate_kernel<<<(nb * 32 + 255) / 256, 256>>>(feat, nb);

    // Fused relation-sum GEMM: out = sum_r H_r @ W_r
    cudaFuncSetAttribute(gemm_kernel,
                         cudaFuncAttributeMaxDynamicSharedMemorySize, SMEM_SZ);
    gemm_kernel<<<(n_nodes + 127) / 128, 512, SMEM_SZ>>>(out, n_nodes);
}